// round 12
// baseline (speedup 1.0000x reference)
#include <cuda_runtime.h>
#include <cuda_bf16.h>
#include <cstdint>

#define Nn 19
#define GH 64
#define GE 64
#define Bb 256
#define Tt 256
#define BT (Bb*Tt)
#define LH 64
#define G4 256  // 4*LH

typedef unsigned long long ull;

// Scratch (device globals; no allocation allowed)
__device__ float g_emb[(size_t)BT * GE];     // (B*T, 64)
__device__ float g_xg0[(size_t)BT * G4];     // (B*T, 256)

// ---- packed f32x2 helpers -------------------------------------------------
__device__ __forceinline__ ull pk2(float lo, float hi) {
    ull r; asm("mov.b64 %0, {%1, %2};" : "=l"(r) : "f"(lo), "f"(hi)); return r;
}
__device__ __forceinline__ void upk2(ull v, float& lo, float& hi) {
    asm("mov.b64 {%0, %1}, %2;" : "=f"(lo), "=f"(hi) : "l"(v));
}
__device__ __forceinline__ ull fma2_(ull a, ull b, ull c) {
    ull d; asm("fma.rn.f32x2 %0, %1, %2, %3;" : "=l"(d) : "l"(a), "l"(b), "l"(c));
    return d;
}

// ---- fast transcendentals via MUFU tanh -----------------------------------
__device__ __forceinline__ float tanh_ap(float x) {
    float y; asm("tanh.approx.f32 %0, %1;" : "=f"(y) : "f"(x)); return y;
}
__device__ __forceinline__ float sigmoidf_(float x) {
    return fmaf(0.5f, tanh_ap(0.5f * x), 0.5f);
}

// ---------------------------------------------------------------------------
// Kernel 1: graph encoder. CTA = 2 warps; EACH WARP processes TWO graphs
// (half-warp per graph). Lane l (0..15) of each half owns feature columns
// l, l+16, l+32, l+48 -> every operand-row LDS.128 feeds 40 FFMA2 and the two
// halves read different graph buffers (disjoint banks -> 1 wavefront).
// Node dim f32x2-packed (rows padded 19->20). Weights in CTA-shared float4
// tables. An overwrites A in place (H1 computed first).
//   per-warp A buffers: offset 380 floats (1520B = 112 mod 128) -> no overlap
//   per-warp X1 buffers: 1284 floats (5136B = 16 mod 128)       -> no overlap
// smem/CTA ~47.1KB -> 4 CTAs/SM; launch_bounds(64,4) -> 256-reg cap.
// ---------------------------------------------------------------------------
__global__ __launch_bounds__(64, 4)
void encoder_kernel(const float* __restrict__ conn, const int* __restrict__ mask,
                    const float* __restrict__ w1_w, const float* __restrict__ w1_b,
                    const float* __restrict__ w2_w, const float* __restrict__ w2_b)
{
    __shared__ __align__(16) float4 w2s4[GE][16];   // [f][l] = w2[{l,l+16,l+32,l+48}][f]
    __shared__ __align__(16) float4 w1s4[Nn][16];   // [k][l] = w1[{l,...}][k]
    __shared__ __align__(16) float As_[2][2 * 380]; // [warp][graph-half offset 380]
    __shared__ __align__(16) float X1_[2][2 * 1284];// [warp][graph-half offset 1284]
    __shared__ float dis_[2][2][20];

    const int tid  = threadIdx.x;
    const int w    = tid >> 5;    // warp in CTA
    const int t    = tid & 31;    // lane
    const int half = t >> 4;      // graph within warp
    const int l    = t & 15;      // lane within half

    // one-time cooperative weight staging (CTA-wide)
    for (int idx = tid; idx < GE * 16; idx += 64) {
        int f = idx >> 4, j = idx & 15;
        w2s4[f][j] = make_float4(w2_w[j * GE + f], w2_w[(j + 16) * GE + f],
                                 w2_w[(j + 32) * GE + f], w2_w[(j + 48) * GE + f]);
    }
    for (int idx = tid; idx < Nn * 16; idx += 64) {
        int k = idx >> 4, j = idx & 15;
        w1s4[k][j] = make_float4(w1_w[j * Nn + k], w1_w[(j + 16) * Nn + k],
                                 w1_w[(j + 32) * Nn + k], w1_w[(j + 48) * Nn + k]);
    }

    float* Ag   = As_[w] + half * 380;    // [k][i] stride 20
    float* X1g  = X1_[w] + half * 1284;   // [f][i] stride 20
    float* disg = dis_[w][half];

    // pad lane i=19 (never rewritten: loads/normalize touch i<19 only)
    if (l < Nn) Ag[l * 20 + 19] = 0.f;

    // biases (dup-packed) for the 4 owned columns
    ull b1d[4], b2d[4];
#pragma unroll
    for (int c = 0; c < 4; c++) {
        float b1 = w1_b[l + c * 16]; b1d[c] = pk2(b1, b1);
        float b2 = w2_b[l + c * 16]; b2d[c] = pk2(b2, b2);
    }
    __syncthreads();

    const int npair = gridDim.x * 2;
    for (int pair = blockIdx.x * 2 + w; pair < BT / 2; pair += npair) {
        const int bt = pair * 2 + half;

        // ---- load A transposed (each half-warp its own graph) ----
        const float* A = conn + (size_t)bt * (Nn * Nn);
#pragma unroll
        for (int u = 0; u < 23; u++) {
            int idx = l + u * 16;
            if (idx < Nn * Nn) { int i = idx / Nn, k = idx - i * Nn; Ag[k * 20 + i] = A[idx]; }
        }
        __syncwarp();
        // ---- degree normalization factors ----
#pragma unroll
        for (int n = l; n < Nn; n += 16) {
            float d = 1.f;
#pragma unroll
            for (int k = 0; k < Nn; k++) d += Ag[k * 20 + n];
            disg[n] = rsqrtf(fmaxf(d, 1e-6f));
        }
        __syncwarp();

        // ---- H1 = A@W1^T + b1 (reads raw A) ----
        ull ac[4][10];
#pragma unroll
        for (int c = 0; c < 4; c++)
#pragma unroll
            for (int p = 0; p < 10; p++) ac[c][p] = b1d[c];
#pragma unroll
        for (int k = 0; k < Nn; k++) {
            float4 wv = w1s4[k][l];
            ull w0 = pk2(wv.x, wv.x), w1 = pk2(wv.y, wv.y);
            ull w2 = pk2(wv.z, wv.z), w3 = pk2(wv.w, wv.w);
            const ulonglong2* row = (const ulonglong2*)(Ag + k * 20);
#pragma unroll
            for (int q = 0; q < 5; q++) {
                ulonglong2 r = row[q];
                ac[0][2*q] = fma2_(r.x, w0, ac[0][2*q]); ac[0][2*q+1] = fma2_(r.y, w0, ac[0][2*q+1]);
                ac[1][2*q] = fma2_(r.x, w1, ac[1][2*q]); ac[1][2*q+1] = fma2_(r.y, w1, ac[1][2*q+1]);
                ac[2][2*q] = fma2_(r.x, w2, ac[2][2*q]); ac[2][2*q+1] = fma2_(r.y, w2, ac[2][2*q+1]);
                ac[3][2*q] = fma2_(r.x, w3, ac[3][2*q]); ac[3][2*q+1] = fma2_(r.y, w3, ac[3][2*q+1]);
            }
        }
        float Hs[4][20];
#pragma unroll
        for (int c = 0; c < 4; c++)
#pragma unroll
            for (int p = 0; p < 10; p++) upk2(ac[c][p], Hs[c][2*p], Hs[c][2*p+1]);
        __syncwarp();   // all lanes done reading raw A

        // ---- normalize A -> An IN PLACE ----
#pragma unroll
        for (int u = 0; u < 23; u++) {
            int idx = l + u * 16;
            if (idx < Nn * Nn) {
                int i = idx / Nn, k = idx - i * Nn;
                float a = Ag[k * 20 + i] + (i == k ? 1.f : 0.f);
                Ag[k * 20 + i] = a * disg[i] * disg[k];
            }
        }
        __syncwarp();

        // ---- X1 = relu(An @ H1) -> X1T smem ----
#pragma unroll
        for (int c = 0; c < 4; c++)
#pragma unroll
            for (int p = 0; p < 10; p++) ac[c][p] = 0ull;
#pragma unroll
        for (int k = 0; k < Nn; k++) {
            ull h0 = pk2(Hs[0][k], Hs[0][k]), h1 = pk2(Hs[1][k], Hs[1][k]);
            ull h2 = pk2(Hs[2][k], Hs[2][k]), h3 = pk2(Hs[3][k], Hs[3][k]);
            const ulonglong2* row = (const ulonglong2*)(Ag + k * 20);
#pragma unroll
            for (int q = 0; q < 5; q++) {
                ulonglong2 r = row[q];
                ac[0][2*q] = fma2_(r.x, h0, ac[0][2*q]); ac[0][2*q+1] = fma2_(r.y, h0, ac[0][2*q+1]);
                ac[1][2*q] = fma2_(r.x, h1, ac[1][2*q]); ac[1][2*q+1] = fma2_(r.y, h1, ac[1][2*q+1]);
                ac[2][2*q] = fma2_(r.x, h2, ac[2][2*q]); ac[2][2*q+1] = fma2_(r.y, h2, ac[2][2*q+1]);
                ac[3][2*q] = fma2_(r.x, h3, ac[3][2*q]); ac[3][2*q+1] = fma2_(r.y, h3, ac[3][2*q+1]);
            }
        }
#pragma unroll
        for (int c = 0; c < 4; c++) {
            float* dst = X1g + (l + c * 16) * 20;
#pragma unroll
            for (int p = 0; p < 10; p++) {
                float lo, hi; upk2(ac[c][p], lo, hi);
                float2 s; s.x = fmaxf(lo, 0.f); s.y = fmaxf(hi, 0.f);
                *(float2*)(dst + 2 * p) = s;
            }
        }
        __syncwarp();

        // ---- H2 = X1@W2^T + b2 ----
#pragma unroll
        for (int c = 0; c < 4; c++)
#pragma unroll
            for (int p = 0; p < 10; p++) ac[c][p] = b2d[c];
#pragma unroll 8
        for (int f = 0; f < GE; f++) {
            float4 wv = w2s4[f][l];
            ull w0 = pk2(wv.x, wv.x), w1 = pk2(wv.y, wv.y);
            ull w2 = pk2(wv.z, wv.z), w3 = pk2(wv.w, wv.w);
            const ulonglong2* row = (const ulonglong2*)(X1g + f * 20);
#pragma unroll
            for (int q = 0; q < 5; q++) {
                ulonglong2 r = row[q];
                ac[0][2*q] = fma2_(r.x, w0, ac[0][2*q]); ac[0][2*q+1] = fma2_(r.y, w0, ac[0][2*q+1]);
                ac[1][2*q] = fma2_(r.x, w1, ac[1][2*q]); ac[1][2*q+1] = fma2_(r.y, w1, ac[1][2*q+1]);
                ac[2][2*q] = fma2_(r.x, w2, ac[2][2*q]); ac[2][2*q+1] = fma2_(r.y, w2, ac[2][2*q+1]);
                ac[3][2*q] = fma2_(r.x, w3, ac[3][2*q]); ac[3][2*q+1] = fma2_(r.y, w3, ac[3][2*q+1]);
            }
        }
#pragma unroll
        for (int c = 0; c < 4; c++)
#pragma unroll
            for (int p = 0; p < 10; p++) upk2(ac[c][p], Hs[c][2*p], Hs[c][2*p+1]);

        // ---- X2 = relu(An @ H2); mean over nodes; mask ----
#pragma unroll
        for (int c = 0; c < 4; c++)
#pragma unroll
            for (int p = 0; p < 10; p++) ac[c][p] = 0ull;
#pragma unroll
        for (int k = 0; k < Nn; k++) {
            ull h0 = pk2(Hs[0][k], Hs[0][k]), h1 = pk2(Hs[1][k], Hs[1][k]);
            ull h2 = pk2(Hs[2][k], Hs[2][k]), h3 = pk2(Hs[3][k], Hs[3][k]);
            const ulonglong2* row = (const ulonglong2*)(Ag + k * 20);
#pragma unroll
            for (int q = 0; q < 5; q++) {
                ulonglong2 r = row[q];
                ac[0][2*q] = fma2_(r.x, h0, ac[0][2*q]); ac[0][2*q+1] = fma2_(r.y, h0, ac[0][2*q+1]);
                ac[1][2*q] = fma2_(r.x, h1, ac[1][2*q]); ac[1][2*q+1] = fma2_(r.y, h1, ac[1][2*q+1]);
                ac[2][2*q] = fma2_(r.x, h2, ac[2][2*q]); ac[2][2*q+1] = fma2_(r.y, h2, ac[2][2*q+1]);
                ac[3][2*q] = fma2_(r.x, h3, ac[3][2*q]); ac[3][2*q+1] = fma2_(r.y, h3, ac[3][2*q+1]);
            }
        }
        const float mf = (float)mask[bt] * (1.f / 19.f);
#pragma unroll
        for (int c = 0; c < 4; c++) {
            float s = 0.f;
#pragma unroll
            for (int p = 0; p < 10; p++) {
                float lo, hi; upk2(ac[c][p], lo, hi);
                s += fmaxf(lo, 0.f) + fmaxf(hi, 0.f);   // pad node contributes 0
            }
            g_emb[(size_t)bt * GE + l + c * 16] = s * mf;
        }
        __syncwarp();   // protect per-warp smem before next pair
    }
}

// ---------------------------------------------------------------------------
// Kernel 2: xg0 = emb @ Wih0^T + (bih0+bhh0); ulonglong2 operand loads.
// ---------------------------------------------------------------------------
__global__ __launch_bounds__(128, 2)
void xg_kernel(const float* __restrict__ Wih0, const float* __restrict__ bih0,
               const float* __restrict__ bhh0)
{
    __shared__ __align__(16) float es[64 * GE];
    const int t = threadIdx.x;
    ull wp1[GE / 2], wp2[GE / 2];
#pragma unroll
    for (int k2 = 0; k2 < GE / 2; k2++)
        wp1[k2] = pk2(Wih0[t * GE + 2*k2], Wih0[t * GE + 2*k2 + 1]);
#pragma unroll
    for (int k2 = 0; k2 < GE / 2; k2++)
        wp2[k2] = pk2(Wih0[(t + 128) * GE + 2*k2], Wih0[(t + 128) * GE + 2*k2 + 1]);
    const float bias1 = bih0[t] + bhh0[t];
    const float bias2 = bih0[t + 128] + bhh0[t + 128];

    const float* ep = g_emb + (size_t)blockIdx.x * 64 * GE;
    for (int idx = t; idx < 64 * GE; idx += 128) es[idx] = ep[idx];
    __syncthreads();

    float* op = g_xg0 + (size_t)blockIdx.x * 64 * G4;
    for (int r = 0; r < 64; r++) {
        ull a1 = pk2(bias1, 0.f), a2 = pk2(bias2, 0.f);
        const ulonglong2* row = (const ulonglong2*)&es[r * GE];
#pragma unroll
        for (int q = 0; q < 16; q++) {
            ulonglong2 e = row[q];
            a1 = fma2_(e.x, wp1[2*q],     a1);
            a1 = fma2_(e.y, wp1[2*q + 1], a1);
            a2 = fma2_(e.x, wp2[2*q],     a2);
            a2 = fma2_(e.y, wp2[2*q + 1], a2);
        }
        float lo, hi;
        upk2(a1, lo, hi); op[r * G4 + t]       = lo + hi;
        upk2(a2, lo, hi); op[r * G4 + t + 128] = lo + hi;
    }
}

// ---------------------------------------------------------------------------
// Kernel 3: fused 2-layer LSTM + FC head — R11 version (384 threads,
// 3-group pipeline, MUFU tanh.approx). Unchanged.
// ---------------------------------------------------------------------------
__global__ __launch_bounds__(384, 1)
void lstm_kernel(const int* __restrict__ mask,
                 const float* __restrict__ Whh0,
                 const float* __restrict__ Wih1, const float* __restrict__ Whh1,
                 const float* __restrict__ bih1, const float* __restrict__ bhh1,
                 const float* __restrict__ fc1_w, const float* __restrict__ fc1_b,
                 const float* __restrict__ fc2_w, const float* __restrict__ fc2_b,
                 float* __restrict__ out)
{
    __shared__ __align__(16) float h0s[2][LH];
    __shared__ __align__(16) float h1s[2][LH];
    __shared__ float c0s[2][LH], c1s[2][LH];
    __shared__ float a0buf[2][G4], p1buf[2][G4], p2buf[2][G4];
    __shared__ float lasth[2][LH];
    __shared__ float r1s[2][32];
    __shared__ int lastidx[2];

    const int tid = threadIdx.x;
    const int m = tid >> 7;
    const int g = tid & 127;
    const int b0 = blockIdx.x * 2;

    const float* W = (m == 0) ? Whh0 : (m == 1) ? Wih1 : Whh1;
    ull wap[LH / 2], wbp[LH / 2];
#pragma unroll
    for (int k2 = 0; k2 < LH / 2; k2++)
        wap[k2] = pk2(W[g * LH + 2*k2], W[g * LH + 2*k2 + 1]);
#pragma unroll
    for (int k2 = 0; k2 < LH / 2; k2++)
        wbp[k2] = pk2(W[(g + 128) * LH + 2*k2], W[(g + 128) * LH + 2*k2 + 1]);
    float biasA = 0.f, biasB = 0.f;
    if (m == 2) { biasA = bih1[g] + bhh1[g]; biasB = bih1[g + 128] + bhh1[g + 128]; }

    if (tid < 2 * LH) {
        int bb = tid >> 6, j = tid & 63;
        h0s[bb][j] = 0.f; c0s[bb][j] = 0.f;
        h1s[bb][j] = 0.f; c1s[bb][j] = 0.f;
        lasth[bb][j] = 0.f;
    }
    if (tid < 2) {
        const int* mp = mask + (size_t)(b0 + tid) * Tt;
        int sum = 0;
        for (int tt = 0; tt < Tt; tt++) sum += mp[tt];
        lastidx[tid] = max(sum, 1) - 1;
    }
    __syncthreads();

    float xga[2], xgb[2];
    if (m == 0) {
#pragma unroll
        for (int bb = 0; bb < 2; bb++) {
            const float* xp = g_xg0 + (size_t)(b0 + bb) * Tt * G4;
            xga[bb] = xp[g]; xgb[bb] = xp[g + 128];
        }
    }

    for (int s = 0; s <= Tt; s++) {
        if (m == 0) {
            if (s < Tt) {
#pragma unroll
                for (int bb = 0; bb < 2; bb++) {
                    ull aA = pk2(xga[bb], 0.f), aB = pk2(xgb[bb], 0.f);
                    const ulonglong2* hp = (const ulonglong2*)h0s[bb];
#pragma unroll
                    for (int q = 0; q < 16; q++) {
                        ulonglong2 h = hp[q];
                        aA = fma2_(h.x, wap[2*q],     aA);
                        aA = fma2_(h.y, wap[2*q + 1], aA);
                        aB = fma2_(h.x, wbp[2*q],     aB);
                        aB = fma2_(h.y, wbp[2*q + 1], aB);
                    }
                    float lo, hi;
                    upk2(aA, lo, hi); a0buf[bb][g]       = lo + hi;
                    upk2(aB, lo, hi); a0buf[bb][g + 128] = lo + hi;
                }
                if (s + 1 < Tt) {
#pragma unroll
                    for (int bb = 0; bb < 2; bb++) {
                        const float* xp = g_xg0 + ((size_t)(b0 + bb) * Tt + (s + 1)) * G4;
                        xga[bb] = xp[g]; xgb[bb] = xp[g + 128];
                    }
                }
            }
        } else if (m == 1) {
            if (s >= 1) {
#pragma unroll
                for (int bb = 0; bb < 2; bb++) {
                    ull aA = 0ull, aB = 0ull;
                    const ulonglong2* hp = (const ulonglong2*)h0s[bb];
#pragma unroll
                    for (int q = 0; q < 16; q++) {
                        ulonglong2 h = hp[q];
                        aA = fma2_(h.x, wap[2*q],     aA);
                        aA = fma2_(h.y, wap[2*q + 1], aA);
                        aB = fma2_(h.x, wbp[2*q],     aB);
                        aB = fma2_(h.y, wbp[2*q + 1], aB);
                    }
                    float lo, hi;
                    upk2(aA, lo, hi); p1buf[bb][g]       = lo + hi;
                    upk2(aB, lo, hi); p1buf[bb][g + 128] = lo + hi;
                }
            }
        } else {
            if (s >= 1) {
#pragma unroll
                for (int bb = 0; bb < 2; bb++) {
                    ull aA = pk2(biasA, 0.f), aB = pk2(biasB, 0.f);
                    const ulonglong2* hp = (const ulonglong2*)h1s[bb];
#pragma unroll
                    for (int q = 0; q < 16; q++) {
                        ulonglong2 h = hp[q];
                        aA = fma2_(h.x, wap[2*q],     aA);
                        aA = fma2_(h.y, wap[2*q + 1], aA);
                        aB = fma2_(h.x, wbp[2*q],     aB);
                        aB = fma2_(h.y, wbp[2*q + 1], aB);
                    }
                    float lo, hi;
                    upk2(aA, lo, hi); p2buf[bb][g]       = lo + hi;
                    upk2(aB, lo, hi); p2buf[bb][g + 128] = lo + hi;
                }
            }
        }
        __syncthreads();

        if (m == 0 && s < Tt) {
            int bb = g >> 6, j = g & 63;
            float gi = a0buf[bb][j];
            float gf = a0buf[bb][j + 64];
            float gg = a0buf[bb][j + 128];
            float go = a0buf[bb][j + 192];
            float c = sigmoidf_(gf) * c0s[bb][j] + sigmoidf_(gi) * tanh_ap(gg);
            c0s[bb][j] = c;
            h0s[bb][j] = sigmoidf_(go) * tanh_ap(c);
        }
        if (m == 1 && s >= 1) {
            int bb = g >> 6, j = g & 63;
            float gi = p1buf[bb][j]       + p2buf[bb][j];
            float gf = p1buf[bb][j + 64]  + p2buf[bb][j + 64];
            float gg = p1buf[bb][j + 128] + p2buf[bb][j + 128];
            float go = p1buf[bb][j + 192] + p2buf[bb][j + 192];
            float c = sigmoidf_(gf) * c1s[bb][j] + sigmoidf_(gi) * tanh_ap(gg);
            c1s[bb][j] = c;
            float h = sigmoidf_(go) * tanh_ap(c);
            h1s[bb][j] = h;
            if (s - 1 == lastidx[bb]) lasth[bb][j] = h;
        }
        __syncthreads();
    }

    if (tid < 64) {
        int bb = tid >> 5, j = tid & 31;
        float acc = fc1_b[j];
#pragma unroll
        for (int k = 0; k < LH; k++) acc = fmaf(lasth[bb][k], fc1_w[j * LH + k], acc);
        r1s[bb][j] = fmaxf(acc, 0.f);
    }
    __syncthreads();
    if (tid < 4) {
        int bb = tid >> 1, o = tid & 1;
        float acc = fc2_b[o];
#pragma unroll
        for (int k = 0; k < 32; k++) acc = fmaf(r1s[bb][k], fc2_w[o * 32 + k], acc);
        out[(b0 + bb) * 2 + o] = acc;
    }
}

// ---------------------------------------------------------------------------
extern "C" void kernel_launch(void* const* d_in, const int* in_sizes, int n_in,
                              void* d_out, int out_size)
{
    const float* conn  = (const float*)d_in[0];
    const int*   mask  = (const int*)  d_in[1];
    const float* w1_w  = (const float*)d_in[2];
    const float* w1_b  = (const float*)d_in[3];
    const float* w2_w  = (const float*)d_in[4];
    const float* w2_b  = (const float*)d_in[5];
    const float* Wih0  = (const float*)d_in[6];
    const float* Whh0  = (const float*)d_in[7];
    const float* bih0  = (const float*)d_in[8];
    const float* bhh0  = (const float*)d_in[9];
    const float* Wih1  = (const float*)d_in[10];
    const float* Whh1  = (const float*)d_in[11];
    const float* bih1  = (const float*)d_in[12];
    const float* bhh1  = (const float*)d_in[13];
    const float* fc1_w = (const float*)d_in[14];
    const float* fc1_b = (const float*)d_in[15];
    const float* fc2_w = (const float*)d_in[16];
    const float* fc2_b = (const float*)d_in[17];
    float* out = (float*)d_out;

    (void)cudaFuncSetAttribute((const void*)encoder_kernel,
                               cudaFuncAttributePreferredSharedMemoryCarveout, 100);

    // 4 CTAs/SM x 148 SMs = 592 CTAs; each warp handles a pair of graphs
    encoder_kernel<<<592, 64>>>(conn, mask, w1_w, w1_b, w2_w, w2_b);
    xg_kernel<<<BT / 64, 128>>>(Wih0, bih0, bhh0);
    lstm_kernel<<<Bb / 2, 384>>>(mask, Whh0, Wih1, Whh1, bih1, bhh1,
                                 fc1_w, fc1_b, fc2_w, fc2_b, out);
}